// round 5
// baseline (speedup 1.0000x reference)
#include <cuda_runtime.h>
#include <cstdint>

#define H 4096
#define INF 4096
#define OUTF 4096
#define KRED 256
#define NRED 16

// Reduced operands (tf32-rounded fp32) in k-PERMUTED layout:
// within each 8-col group, position 2*(k&3)+((k>>2)&1) holds col k.
__device__ float g_xs[H * KRED];
__device__ float g_wsT[OUTF * KRED];

__device__ __forceinline__ float to_tf32(float x) {
    float r;
    asm("cvt.rna.tf32.f32 %0, %1;" : "=f"(r) : "f"(x));
    return r;
}

// ---------------------------------------------------------------------------
// Fused reduction with permuted stores.
// ---------------------------------------------------------------------------
__global__ void __launch_bounds__(256) lin_reduce(const float* __restrict__ x,
                                                  const float* __restrict__ w) {
    int b = blockIdx.x;
    const float* src;
    float* dst;
    if (b < 1024) { src = x; dst = g_xs; }
    else          { src = w; dst = g_wsT; b -= 1024; }
    const int row = b * 4 + (threadIdx.x >> 6);
    const int p = (threadIdx.x & 63) * 4;
    const float4* s = (const float4*)(src + (size_t)row * INF + p);
    float4 a = make_float4(0.f, 0.f, 0.f, 0.f);
#pragma unroll
    for (int v = 0; v < NRED; v++) {
        float4 t = s[v * (KRED / 4)];
        a.x += t.x; a.y += t.y; a.z += t.z; a.w += t.w;
    }
    float* d = dst + (size_t)row * KRED + (p & ~7) + ((p & 4) ? 1 : 0);
    d[0] = to_tf32(a.x);
    d[2] = to_tf32(a.y);
    d[4] = to_tf32(a.z);
    d[6] = to_tf32(a.w);
}

// ---------------------------------------------------------------------------
// GEMM via mma.sync tf32: out = xs(4096x256) @ wsT^T + bias
// CTA 256(M) x 128(N); 512 threads, 16 warps in 4x4 grid; warp tile 64x32.
// 3-stage cp.async pipeline, KC=32.
// ---------------------------------------------------------------------------
#define BM 256
#define BN 128
#define KC 32
#define LDSTR 40
#define A_BUF (BM * LDSTR)              // 10240 floats
#define B_BUF (BN * LDSTR)              // 5120 floats
#define STAGE_F (A_BUF + B_BUF)         // 15360 floats
#define SMEM_FLOATS (3 * STAGE_F + 128)
#define SMEM_BYTES (SMEM_FLOATS * 4)    // 185856 B

__device__ __forceinline__ void mma_tf32(float* d, const uint32_t* a, const uint32_t* b) {
    asm volatile(
        "mma.sync.aligned.m16n8k8.row.col.f32.tf32.tf32.f32 "
        "{%0,%1,%2,%3}, {%4,%5,%6,%7}, {%8,%9}, {%0,%1,%2,%3};\n"
        : "+f"(d[0]), "+f"(d[1]), "+f"(d[2]), "+f"(d[3])
        : "r"(a[0]), "r"(a[1]), "r"(a[2]), "r"(a[3]),
          "r"(b[0]), "r"(b[1]));
}

__device__ __forceinline__ void cp16(uint32_t dst, const float* src) {
    asm volatile("cp.async.cg.shared.global [%0], [%1], 16;"
                 :: "r"(dst), "l"(src) : "memory");
}

__global__ void __launch_bounds__(512, 1)
lin_gemm(const float* __restrict__ bias, float* __restrict__ out) {
    extern __shared__ float sm[];
    float* s_bias = sm + 3 * STAGE_F;

    const int tid = threadIdx.x;
    const int warp = tid >> 5;
    const int lane = tid & 31;
    const int wm = warp >> 2;            // 0..3 -> 64-row slab
    const int wn = warp & 3;             // 0..3 -> 32-col slab
    const int g = lane >> 2;
    const int t = lane & 3;
    const int m0 = blockIdx.y * BM;
    const int n0 = blockIdx.x * BN;

    if (tid < 128) s_bias[tid] = bias[n0 + tid];

    // cooperative-load coords: 64 base rows x 8 float4 columns
    const int lrow = tid >> 3;           // 0..63
    const int lc4 = (tid & 7) * 4;       // 0..28

    const uint32_t smem0 = (uint32_t)__cvta_generic_to_shared(sm);
    const uint32_t aDst0 = smem0 + (lrow * LDSTR + lc4) * 4;
    const uint32_t bDst0 = smem0 + (A_BUF + lrow * LDSTR + lc4) * 4;
    const float* aSrc = g_xs + (size_t)(m0 + lrow) * KRED + lc4;
    const float* bSrc = g_wsT + (size_t)(n0 + lrow) * KRED + lc4;

    float acc[4][4][4];
#pragma unroll
    for (int mt = 0; mt < 4; mt++)
#pragma unroll
        for (int nt = 0; nt < 4; nt++)
#pragma unroll
            for (int i = 0; i < 4; i++) acc[mt][nt][i] = 0.f;

    // prefetch chunks 0 and 1 into stages 0 and 1
#pragma unroll
    for (int pc = 0; pc < 2; pc++) {
        const uint32_t so = pc * STAGE_F * 4;
        const int kc = pc * KC;
#pragma unroll
        for (int r = 0; r < 4; r++)      // A rows lrow + 64r
            cp16(aDst0 + so + r * 64 * LDSTR * 4, aSrc + (size_t)r * 64 * KRED + kc);
#pragma unroll
        for (int r = 0; r < 2; r++)      // B rows lrow + 64r
            cp16(bDst0 + so + r * 64 * LDSTR * 4, bSrc + (size_t)r * 64 * KRED + kc);
        asm volatile("cp.async.commit_group;" ::: "memory");
    }

#pragma unroll
    for (int c = 0; c < 8; c++) {
        if (c < 7) asm volatile("cp.async.wait_group 1;" ::: "memory");
        else       asm volatile("cp.async.wait_group 0;" ::: "memory");
        __syncthreads();

        if (c < 6) {
            const int ns = (c + 2) % 3;
            const uint32_t so = ns * STAGE_F * 4;
            const int kc = (c + 2) * KC;
#pragma unroll
            for (int r = 0; r < 4; r++)
                cp16(aDst0 + so + r * 64 * LDSTR * 4, aSrc + (size_t)r * 64 * KRED + kc);
#pragma unroll
            for (int r = 0; r < 2; r++)
                cp16(bDst0 + so + r * 64 * LDSTR * 4, bSrc + (size_t)r * 64 * KRED + kc);
            asm volatile("cp.async.commit_group;" ::: "memory");
        }

        const float* As = sm + (c % 3) * STAGE_F;
        const float* Bs = As + A_BUF;
        const float* Ab = As + (wm * 64 + g) * LDSTR + 2 * t;
        const float* Bb = Bs + (wn * 32 + g) * LDSTR + 2 * t;

#pragma unroll
        for (int k8 = 0; k8 < 4; k8++) {
            const int kk = k8 * 8;
            uint32_t a[4][4], b[4][2];
#pragma unroll
            for (int mt = 0; mt < 4; mt++) {
                float2 lo = *(const float2*)(Ab + mt * 16 * LDSTR + kk);
                float2 hi = *(const float2*)(Ab + (mt * 16 + 8) * LDSTR + kk);
                a[mt][0] = __float_as_uint(lo.x);
                a[mt][1] = __float_as_uint(hi.x);
                a[mt][2] = __float_as_uint(lo.y);
                a[mt][3] = __float_as_uint(hi.y);
            }
#pragma unroll
            for (int nt = 0; nt < 4; nt++) {
                float2 bb = *(const float2*)(Bb + nt * 8 * LDSTR + kk);
                b[nt][0] = __float_as_uint(bb.x);
                b[nt][1] = __float_as_uint(bb.y);
            }
#pragma unroll
            for (int mt = 0; mt < 4; mt++)
#pragma unroll
                for (int nt = 0; nt < 4; nt++)
                    mma_tf32(acc[mt][nt], a[mt], b[nt]);
        }
    }

    // Epilogue: bias + float2 stores
#pragma unroll
    for (int mt = 0; mt < 4; mt++) {
        const int r0 = m0 + wm * 64 + mt * 16 + g;
#pragma unroll
        for (int nt = 0; nt < 4; nt++) {
            const int col = wn * 32 + nt * 8 + 2 * t;
            const float b0 = s_bias[col], b1 = s_bias[col + 1];
            float2 v0 = make_float2(acc[mt][nt][0] + b0, acc[mt][nt][1] + b1);
            float2 v1 = make_float2(acc[mt][nt][2] + b0, acc[mt][nt][3] + b1);
            *(float2*)&out[(size_t)r0 * OUTF + n0 + col] = v0;
            *(float2*)&out[(size_t)(r0 + 8) * OUTF + n0 + col] = v1;
        }
    }
}

extern "C" void kernel_launch(void* const* d_in, const int* in_sizes, int n_in,
                              void* d_out, int out_size) {
    const float* x = (const float*)d_in[0];
    const float* w = (const float*)d_in[1];
    const float* bias = (const float*)d_in[2];
    float* out = (float*)d_out;

    cudaFuncSetAttribute(lin_gemm, cudaFuncAttributeMaxDynamicSharedMemorySize, SMEM_BYTES);

    lin_reduce<<<2048, 256>>>(x, w);
    dim3 grid(OUTF / BN, H / BM);   // (32, 16)
    lin_gemm<<<grid, 512, SMEM_BYTES>>>(bias, out);
}

// round 6
// speedup vs baseline: 1.2741x; 1.2741x over previous
#include <cuda_runtime.h>
#include <cuda_fp16.h>
#include <cstdint>

#define H 4096
#define INF 4096
#define OUTF 4096
#define KRED 256
#define NRED 16

// Reduced operands in fp16 (fp32-accumulated, then rounded). 2 MB each.
__device__ __half g_xs[H * KRED];     // xs[m][k] row-major
__device__ __half g_wsT[OUTF * KRED]; // wsT[n][k] row-major

// ---------------------------------------------------------------------------
// Fused reduction: blocks [0,1024): x -> g_xs ; [1024,2048): w -> g_wsT.
// 4 rows/block, 64 threads/row, float4 loads, packed half stores.
// ---------------------------------------------------------------------------
__global__ void __launch_bounds__(256) lin_reduce(const float* __restrict__ x,
                                                  const float* __restrict__ w) {
    int b = blockIdx.x;
    const float* src;
    __half* dst;
    if (b < 1024) { src = x; dst = g_xs; }
    else          { src = w; dst = g_wsT; b -= 1024; }
    const int row = b * 4 + (threadIdx.x >> 6);
    const int p = (threadIdx.x & 63) * 4;
    const float4* s = (const float4*)(src + (size_t)row * INF + p);
    float4 a0 = make_float4(0.f, 0.f, 0.f, 0.f);
    float4 a1 = make_float4(0.f, 0.f, 0.f, 0.f);
#pragma unroll
    for (int v = 0; v < NRED; v += 2) {
        float4 t0 = s[v * (KRED / 4)];
        float4 t1 = s[(v + 1) * (KRED / 4)];
        a0.x += t0.x; a0.y += t0.y; a0.z += t0.z; a0.w += t0.w;
        a1.x += t1.x; a1.y += t1.y; a1.z += t1.z; a1.w += t1.w;
    }
    a0.x += a1.x; a0.y += a1.y; a0.z += a1.z; a0.w += a1.w;
    __half2 lo = __floats2half2_rn(a0.x, a0.y);
    __half2 hi = __floats2half2_rn(a0.z, a0.w);
    uint2 pk = make_uint2(*(uint32_t*)&lo, *(uint32_t*)&hi);
    *(uint2*)(dst + (size_t)row * KRED + p) = pk;
}

// ---------------------------------------------------------------------------
// GEMM via mma.sync fp16 (f32 accum): out = xs @ wsT^T + bias
// CTA 256(M) x 128(N); 512 threads, 16 warps 4x4; warp tile 64x32.
// KC=64, 4 chunks, 3-stage cp.async pipeline.
// ---------------------------------------------------------------------------
#define BM 256
#define BN 128
#define KC 64
#define LDSTR 72                        // halves per smem row (144 B, conflict-free)
#define A_BUF (BM * LDSTR)              // 18432 halves
#define B_BUF (BN * LDSTR)              // 9216 halves
#define STAGE_H (A_BUF + B_BUF)         // 27648 halves
#define STAGE_B (STAGE_H * 2)           // 55296 bytes
#define SMEM_BYTES (3 * STAGE_B + 512)  // 166400 B

__device__ __forceinline__ void mma_f16(float* d, const uint32_t* a, const uint32_t* b) {
    asm volatile(
        "mma.sync.aligned.m16n8k16.row.col.f32.f16.f16.f32 "
        "{%0,%1,%2,%3}, {%4,%5,%6,%7}, {%8,%9}, {%0,%1,%2,%3};\n"
        : "+f"(d[0]), "+f"(d[1]), "+f"(d[2]), "+f"(d[3])
        : "r"(a[0]), "r"(a[1]), "r"(a[2]), "r"(a[3]),
          "r"(b[0]), "r"(b[1]));
}

__device__ __forceinline__ void cp16(uint32_t dst, const void* src) {
    asm volatile("cp.async.cg.shared.global [%0], [%1], 16;"
                 :: "r"(dst), "l"(src) : "memory");
}

__global__ void __launch_bounds__(512, 1)
lin_gemm(const float* __restrict__ bias, float* __restrict__ out) {
    extern __shared__ __half smh[];
    float* s_bias = (float*)(smh + 3 * STAGE_H);

    const int tid = threadIdx.x;
    const int warp = tid >> 5;
    const int lane = tid & 31;
    const int wm = warp >> 2;            // 0..3 -> 64-row slab
    const int wn = warp & 3;             // 0..3 -> 32-col slab
    const int g = lane >> 2;
    const int t = lane & 3;
    const int m0 = blockIdx.y * BM;
    const int n0 = blockIdx.x * BN;

    if (tid < 128) s_bias[tid] = bias[n0 + tid];

    // cooperative-load coords: rows tid>>3 (0..63), 8 halves (16B) per thread
    const int lrow = tid >> 3;
    const int lch = (tid & 7) * 8;       // half offset within 64-half chunk row

    const uint32_t smem0 = (uint32_t)__cvta_generic_to_shared(smh);
    const uint32_t aDst0 = smem0 + (lrow * LDSTR + lch) * 2;
    const uint32_t bDst0 = smem0 + (A_BUF + lrow * LDSTR + lch) * 2;
    const __half* aSrc = g_xs + (size_t)(m0 + lrow) * KRED + lch;
    const __half* bSrc = g_wsT + (size_t)(n0 + lrow) * KRED + lch;

    float acc[4][4][4];
#pragma unroll
    for (int mt = 0; mt < 4; mt++)
#pragma unroll
        for (int nt = 0; nt < 4; nt++)
#pragma unroll
            for (int i = 0; i < 4; i++) acc[mt][nt][i] = 0.f;

    // prefetch chunks 0,1 into stages 0,1
#pragma unroll
    for (int pc = 0; pc < 2; pc++) {
        const uint32_t so = pc * STAGE_B;
        const int kc = pc * KC;
#pragma unroll
        for (int r = 0; r < 4; r++)      // A rows lrow + 64r
            cp16(aDst0 + so + r * 64 * LDSTR * 2, aSrc + (size_t)r * 64 * KRED + kc);
#pragma unroll
        for (int r = 0; r < 2; r++)      // B rows lrow + 64r
            cp16(bDst0 + so + r * 64 * LDSTR * 2, bSrc + (size_t)r * 64 * KRED + kc);
        asm volatile("cp.async.commit_group;" ::: "memory");
    }

#pragma unroll
    for (int c = 0; c < 4; c++) {
        if (c < 3) asm volatile("cp.async.wait_group 1;" ::: "memory");
        else       asm volatile("cp.async.wait_group 0;" ::: "memory");
        __syncthreads();

        if (c < 2) {
            const int ns = (c + 2) % 3;
            const uint32_t so = ns * STAGE_B;
            const int kc = (c + 2) * KC;
#pragma unroll
            for (int r = 0; r < 4; r++)
                cp16(aDst0 + so + r * 64 * LDSTR * 2, aSrc + (size_t)r * 64 * KRED + kc);
#pragma unroll
            for (int r = 0; r < 2; r++)
                cp16(bDst0 + so + r * 64 * LDSTR * 2, bSrc + (size_t)r * 64 * KRED + kc);
            asm volatile("cp.async.commit_group;" ::: "memory");
        }

        const __half* As = smh + (c % 3) * STAGE_H;
        const __half* Bs = As + A_BUF;
        const __half* Ab = As + (wm * 64 + g) * LDSTR + 2 * t;
        const __half* Bb = Bs + (wn * 32 + g) * LDSTR + 2 * t;

#pragma unroll
        for (int s = 0; s < 4; s++) {    // 4 k16 steps
            const int kk = s * 16;
            uint32_t a[4][4], b[4][2];
#pragma unroll
            for (int mt = 0; mt < 4; mt++) {
                const __half* p = Ab + mt * 16 * LDSTR + kk;
                a[mt][0] = *(const uint32_t*)(p);
                a[mt][1] = *(const uint32_t*)(p + 8 * LDSTR);
                a[mt][2] = *(const uint32_t*)(p + 8);
                a[mt][3] = *(const uint32_t*)(p + 8 * LDSTR + 8);
            }
#pragma unroll
            for (int nt = 0; nt < 4; nt++) {
                const __half* p = Bb + nt * 8 * LDSTR + kk;
                b[nt][0] = *(const uint32_t*)(p);
                b[nt][1] = *(const uint32_t*)(p + 8);
            }
#pragma unroll
            for (int mt = 0; mt < 4; mt++)
#pragma unroll
                for (int nt = 0; nt < 4; nt++)
                    mma_f16(acc[mt][nt], a[mt], b[nt]);
        }
    }

    // Epilogue: bias + float2 stores
#pragma unroll
    for (int mt = 0; mt < 4; mt++) {
        const int r0 = m0 + wm * 64 + mt * 16 + g;
#pragma unroll
        for (int nt = 0; nt < 4; nt++) {
            const int col = wn * 32 + nt * 8 + 2 * t;
            const float b0 = s_bias[col], b1 = s_bias[col + 1];
            float2 v0 = make_float2(acc[mt][nt][0] + b0, acc[mt][nt][1] + b1);
            float2 v1 = make_float2(acc[mt][nt][2] + b0, acc[mt][nt][3] + b1);
            *(float2*)&out[(size_t)r0 * OUTF + n0 + col] = v0;
            *(float2*)&out[(size_t)(r0 + 8) * OUTF + n0 + col] = v1;
        }
    }
}

extern "C" void kernel_launch(void* const* d_in, const int* in_sizes, int n_in,
                              void* d_out, int out_size) {
    const float* x = (const float*)d_in[0];
    const float* w = (const float*)d_in[1];
    const float* bias = (const float*)d_in[2];
    float* out = (float*)d_out;

    cudaFuncSetAttribute(lin_gemm, cudaFuncAttributeMaxDynamicSharedMemorySize, SMEM_BYTES);

    lin_reduce<<<2048, 256>>>(x, w);
    dim3 grid(OUTF / BN, H / BM);   // (32, 16)
    lin_gemm<<<grid, 512, SMEM_BYTES>>>(bias, out);
}

// round 7
// speedup vs baseline: 1.4623x; 1.1477x over previous
#include <cuda_runtime.h>
#include <cuda_fp16.h>
#include <cstdint>

#define H 4096
#define INF 4096
#define OUTF 4096
#define KRED 256
#define NRED 16

// Reduced operands in fp16 (fp32-accumulated, then rounded). 2 MB each.
__device__ __half g_xs[H * KRED];     // xs[m][k] row-major
__device__ __half g_wsT[OUTF * KRED]; // wsT[n][k] row-major

// ---------------------------------------------------------------------------
// Fused reduction: blocks [0,1024): x -> g_xs ; [1024,2048): w -> g_wsT.
// ---------------------------------------------------------------------------
__global__ void __launch_bounds__(256) lin_reduce(const float* __restrict__ x,
                                                  const float* __restrict__ w) {
    int b = blockIdx.x;
    const float* src;
    __half* dst;
    if (b < 1024) { src = x; dst = g_xs; }
    else          { src = w; dst = g_wsT; b -= 1024; }
    const int row = b * 4 + (threadIdx.x >> 6);
    const int p = (threadIdx.x & 63) * 4;
    const float4* s = (const float4*)(src + (size_t)row * INF + p);
    float4 a0 = make_float4(0.f, 0.f, 0.f, 0.f);
    float4 a1 = make_float4(0.f, 0.f, 0.f, 0.f);
#pragma unroll
    for (int v = 0; v < NRED; v += 2) {
        float4 t0 = s[v * (KRED / 4)];
        float4 t1 = s[(v + 1) * (KRED / 4)];
        a0.x += t0.x; a0.y += t0.y; a0.z += t0.z; a0.w += t0.w;
        a1.x += t1.x; a1.y += t1.y; a1.z += t1.z; a1.w += t1.w;
    }
    a0.x += a1.x; a0.y += a1.y; a0.z += a1.z; a0.w += a1.w;
    __half2 lo = __floats2half2_rn(a0.x, a0.y);
    __half2 hi = __floats2half2_rn(a0.z, a0.w);
    uint2 pk = make_uint2(*(uint32_t*)&lo, *(uint32_t*)&hi);
    *(uint2*)(dst + (size_t)row * KRED + p) = pk;
}

// ---------------------------------------------------------------------------
// GEMM via mma.sync fp16: out = xs @ wsT^T + bias
// CTA 128(M) x 128(N); 256 threads, 8 warps 4x2; warp tile 32x64.
// KC=64, 4 chunks, 3-stage cp.async pipeline. 2 CTAs per SM.
// ---------------------------------------------------------------------------
#define BM 128
#define BN 128
#define KC 64
#define LDSTR 72                        // halves per smem row (144 B)
#define A_BUF (BM * LDSTR)              // 9216 halves
#define B_BUF (BN * LDSTR)              // 9216 halves
#define STAGE_H (A_BUF + B_BUF)         // 18432 halves
#define STAGE_B (STAGE_H * 2)           // 36864 bytes
#define SMEM_BYTES (3 * STAGE_B + 512)  // 111104 B -> 2 CTAs/SM

__device__ __forceinline__ void mma_f16(float* d, const uint32_t* a, const uint32_t* b) {
    asm volatile(
        "mma.sync.aligned.m16n8k16.row.col.f32.f16.f16.f32 "
        "{%0,%1,%2,%3}, {%4,%5,%6,%7}, {%8,%9}, {%0,%1,%2,%3};\n"
        : "+f"(d[0]), "+f"(d[1]), "+f"(d[2]), "+f"(d[3])
        : "r"(a[0]), "r"(a[1]), "r"(a[2]), "r"(a[3]),
          "r"(b[0]), "r"(b[1]));
}

__device__ __forceinline__ void cp16(uint32_t dst, const void* src) {
    asm volatile("cp.async.cg.shared.global [%0], [%1], 16;"
                 :: "r"(dst), "l"(src) : "memory");
}

__global__ void __launch_bounds__(256, 2)
lin_gemm(const float* __restrict__ bias, float* __restrict__ out) {
    extern __shared__ __half smh[];
    float* s_bias = (float*)(smh + 3 * STAGE_H);

    const int tid = threadIdx.x;
    const int warp = tid >> 5;
    const int lane = tid & 31;
    const int wm = warp >> 1;            // 0..3 -> 32-row slab
    const int wn = warp & 1;             // 0..1 -> 64-col slab
    const int g = lane >> 2;
    const int t = lane & 3;
    const int m0 = blockIdx.y * BM;
    const int n0 = blockIdx.x * BN;

    if (tid < 128) s_bias[tid] = bias[n0 + tid];

    // cooperative-load coords: rows tid>>3 (0..31), 8 halves (16B) each
    const int lrow = tid >> 3;
    const int lch = (tid & 7) * 8;

    const uint32_t smem0 = (uint32_t)__cvta_generic_to_shared(smh);
    const uint32_t aDst0 = smem0 + (lrow * LDSTR + lch) * 2;
    const uint32_t bDst0 = smem0 + (A_BUF + lrow * LDSTR + lch) * 2;
    const __half* aSrc = g_xs + (size_t)(m0 + lrow) * KRED + lch;
    const __half* bSrc = g_wsT + (size_t)(n0 + lrow) * KRED + lch;

    float acc[2][8][4];
#pragma unroll
    for (int mt = 0; mt < 2; mt++)
#pragma unroll
        for (int nt = 0; nt < 8; nt++)
#pragma unroll
            for (int i = 0; i < 4; i++) acc[mt][nt][i] = 0.f;

    // prefetch chunks 0,1 into stages 0,1
#pragma unroll
    for (int pc = 0; pc < 2; pc++) {
        const uint32_t so = pc * STAGE_B;
        const int kc = pc * KC;
#pragma unroll
        for (int r = 0; r < 4; r++) {    // A and B rows lrow + 32r
            cp16(aDst0 + so + r * 32 * LDSTR * 2, aSrc + (size_t)r * 32 * KRED + kc);
            cp16(bDst0 + so + r * 32 * LDSTR * 2, bSrc + (size_t)r * 32 * KRED + kc);
        }
        asm volatile("cp.async.commit_group;" ::: "memory");
    }

#pragma unroll
    for (int c = 0; c < 4; c++) {
        if (c < 3) asm volatile("cp.async.wait_group 1;" ::: "memory");
        else       asm volatile("cp.async.wait_group 0;" ::: "memory");
        __syncthreads();

        if (c < 2) {
            const int ns = (c + 2) % 3;
            const uint32_t so = ns * STAGE_B;
            const int kc = (c + 2) * KC;
#pragma unroll
            for (int r = 0; r < 4; r++) {
                cp16(aDst0 + so + r * 32 * LDSTR * 2, aSrc + (size_t)r * 32 * KRED + kc);
                cp16(bDst0 + so + r * 32 * LDSTR * 2, bSrc + (size_t)r * 32 * KRED + kc);
            }
            asm volatile("cp.async.commit_group;" ::: "memory");
        }

        const __half* As = smh + (c % 3) * STAGE_H;
        const __half* Bs = As + A_BUF;
        const __half* Ab = As + (wm * 32 + g) * LDSTR + 2 * t;
        const __half* Bb = Bs + (wn * 64 + g) * LDSTR + 2 * t;

#pragma unroll
        for (int s = 0; s < 4; s++) {    // 4 k16 steps
            const int kk = s * 16;
            uint32_t a[2][4], b[8][2];
#pragma unroll
            for (int mt = 0; mt < 2; mt++) {
                const __half* p = Ab + mt * 16 * LDSTR + kk;
                a[mt][0] = *(const uint32_t*)(p);
                a[mt][1] = *(const uint32_t*)(p + 8 * LDSTR);
                a[mt][2] = *(const uint32_t*)(p + 8);
                a[mt][3] = *(const uint32_t*)(p + 8 * LDSTR + 8);
            }
#pragma unroll
            for (int nt = 0; nt < 8; nt++) {
                const __half* p = Bb + nt * 8 * LDSTR + kk;
                b[nt][0] = *(const uint32_t*)(p);
                b[nt][1] = *(const uint32_t*)(p + 8);
            }
#pragma unroll
            for (int mt = 0; mt < 2; mt++)
#pragma unroll
                for (int nt = 0; nt < 8; nt++)
                    mma_f16(acc[mt][nt], a[mt], b[nt]);
        }
    }

    // Epilogue: bias + float2 stores
#pragma unroll
    for (int mt = 0; mt < 2; mt++) {
        const int r0 = m0 + wm * 32 + mt * 16 + g;
#pragma unroll
        for (int nt = 0; nt < 8; nt++) {
            const int col = wn * 64 + nt * 8 + 2 * t;
            const float b0 = s_bias[col], b1 = s_bias[col + 1];
            float2 v0 = make_float2(acc[mt][nt][0] + b0, acc[mt][nt][1] + b1);
            float2 v1 = make_float2(acc[mt][nt][2] + b0, acc[mt][nt][3] + b1);
            *(float2*)&out[(size_t)r0 * OUTF + n0 + col] = v0;
            *(float2*)&out[(size_t)(r0 + 8) * OUTF + n0 + col] = v1;
        }
    }
}

extern "C" void kernel_launch(void* const* d_in, const int* in_sizes, int n_in,
                              void* d_out, int out_size) {
    const float* x = (const float*)d_in[0];
    const float* w = (const float*)d_in[1];
    const float* bias = (const float*)d_in[2];
    float* out = (float*)d_out;

    cudaFuncSetAttribute(lin_gemm, cudaFuncAttributeMaxDynamicSharedMemorySize, SMEM_BYTES);

    lin_reduce<<<2048, 256>>>(x, w);
    dim3 grid(OUTF / BN, H / BM);   // (32, 32)
    lin_gemm<<<grid, 256, SMEM_BYTES>>>(bias, out);
}

// round 8
// speedup vs baseline: 1.4630x; 1.0005x over previous
#include <cuda_runtime.h>
#include <cuda_fp16.h>
#include <cstdint>

#define H 4096
#define INF 4096
#define OUTF 4096
#define KRED 256
#define NRED 16

// Reduced operands in fp16. 2 MB each -> L2-resident through the GEMM.
__device__ __half g_xs[H * KRED];     // xs[m][k] row-major
__device__ __half g_wsT[OUTF * KRED]; // wsT[n][k] row-major

// ---------------------------------------------------------------------------
// Fused reduction. Inputs loaded with evict-first (.cs) to avoid polluting L2.
// ---------------------------------------------------------------------------
__device__ __forceinline__ float4 ldcs4(const float4* p) {
    float4 v;
    asm volatile("ld.global.cs.v4.f32 {%0,%1,%2,%3}, [%4];"
                 : "=f"(v.x), "=f"(v.y), "=f"(v.z), "=f"(v.w) : "l"(p));
    return v;
}

__global__ void __launch_bounds__(256) lin_reduce(const float* __restrict__ x,
                                                  const float* __restrict__ w) {
    int b = blockIdx.x;
    const float* src;
    __half* dst;
    if (b < 1024) { src = x; dst = g_xs; }
    else          { src = w; dst = g_wsT; b -= 1024; }
    const int row = b * 4 + (threadIdx.x >> 6);
    const int p = (threadIdx.x & 63) * 4;
    const float4* s = (const float4*)(src + (size_t)row * INF + p);
    float4 a0 = make_float4(0.f, 0.f, 0.f, 0.f);
    float4 a1 = make_float4(0.f, 0.f, 0.f, 0.f);
#pragma unroll
    for (int v = 0; v < NRED; v += 2) {
        float4 t0 = ldcs4(s + v * (KRED / 4));
        float4 t1 = ldcs4(s + (v + 1) * (KRED / 4));
        a0.x += t0.x; a0.y += t0.y; a0.z += t0.z; a0.w += t0.w;
        a1.x += t1.x; a1.y += t1.y; a1.z += t1.z; a1.w += t1.w;
    }
    a0.x += a1.x; a0.y += a1.y; a0.z += a1.z; a0.w += a1.w;
    __half2 lo = __floats2half2_rn(a0.x, a0.y);
    __half2 hi = __floats2half2_rn(a0.z, a0.w);
    uint2 pk = make_uint2(*(uint32_t*)&lo, *(uint32_t*)&hi);
    *(uint2*)(dst + (size_t)row * KRED + p) = pk;
}

// ---------------------------------------------------------------------------
// Persistent GEMM via mma.sync fp16: out = xs @ wsT^T + bias
// CTA 128x128, 256 threads, 8 warps 4x2, warp tile 32x64.
// KC=64, 4 chunks/tile, 3-stage cp.async pipeline CONTINUOUS across tiles.
// ---------------------------------------------------------------------------
#define BM 128
#define BN 128
#define KC 64
#define NTILES 1024                     // 32 x 32
#define LDSTR 72
#define A_BUF (BM * LDSTR)
#define B_BUF (BN * LDSTR)
#define STAGE_H (A_BUF + B_BUF)         // 18432 halves
#define STAGE_B (STAGE_H * 2)           // 36864 B
#define SMEM_BYTES (3 * STAGE_B)        // 110592 B -> 2 CTAs/SM

__device__ __forceinline__ void mma_f16(float* d, const uint32_t* a, const uint32_t* b) {
    asm volatile(
        "mma.sync.aligned.m16n8k16.row.col.f32.f16.f16.f32 "
        "{%0,%1,%2,%3}, {%4,%5,%6,%7}, {%8,%9}, {%0,%1,%2,%3};\n"
        : "+f"(d[0]), "+f"(d[1]), "+f"(d[2]), "+f"(d[3])
        : "r"(a[0]), "r"(a[1]), "r"(a[2]), "r"(a[3]),
          "r"(b[0]), "r"(b[1]));
}

__device__ __forceinline__ void cp16(uint32_t dst, const void* src) {
    asm volatile("cp.async.cg.shared.global [%0], [%1], 16;"
                 :: "r"(dst), "l"(src) : "memory");
}

__global__ void __launch_bounds__(256, 2)
lin_gemm(const float* __restrict__ bias, float* __restrict__ out) {
    extern __shared__ __half smh[];

    const int tid = threadIdx.x;
    const int warp = tid >> 5;
    const int lane = tid & 31;
    const int wm = warp >> 1;
    const int wn = warp & 1;
    const int g = lane >> 2;
    const int t = lane & 3;

    const int lrow = tid >> 3;           // 0..31
    const int lch = (tid & 7) * 8;
    const uint32_t smem0 = (uint32_t)__cvta_generic_to_shared(smh);
    const uint32_t aDst0 = smem0 + (lrow * LDSTR + lch) * 2;
    const uint32_t bDst0 = smem0 + (A_BUF + lrow * LDSTR + lch) * 2;

    // Prefetch state (global over the CTA's whole tile sequence)
    int pfTile = blockIdx.x;
    int pfChunk = 0;
    int sg = 0;                          // next prefetch stage

    auto prefetch = [&]() {
        const int m0 = (pfTile >> 5) * BM;
        const int n0 = (pfTile & 31) * BN;
        const int kc = pfChunk * KC;
        const uint32_t so = sg * STAGE_B;
        const __half* aS = g_xs + (size_t)(m0 + lrow) * KRED + lch + kc;
        const __half* bS = g_wsT + (size_t)(n0 + lrow) * KRED + lch + kc;
#pragma unroll
        for (int r = 0; r < 4; r++) {
            cp16(aDst0 + so + r * 32 * LDSTR * 2, aS + (size_t)r * 32 * KRED);
            cp16(bDst0 + so + r * 32 * LDSTR * 2, bS + (size_t)r * 32 * KRED);
        }
        asm volatile("cp.async.commit_group;" ::: "memory");
        if (++pfChunk == 4) { pfChunk = 0; pfTile += gridDim.x; }
        sg = (sg == 2) ? 0 : sg + 1;
    };

    if (pfTile < NTILES) prefetch();
    if (pfTile < NTILES) prefetch();

    int cs = 0;                          // compute stage

    for (int tile = blockIdx.x; tile < NTILES; tile += gridDim.x) {
        const int m0 = (tile >> 5) * BM;
        const int n0 = (tile & 31) * BN;

        float acc[2][8][4];
#pragma unroll
        for (int mt = 0; mt < 2; mt++)
#pragma unroll
            for (int nt = 0; nt < 8; nt++)
#pragma unroll
                for (int i = 0; i < 4; i++) acc[mt][nt][i] = 0.f;

        const bool lastTile = (tile + gridDim.x >= NTILES);

#pragma unroll
        for (int c = 0; c < 4; c++) {
            if (lastTile && c == 3) asm volatile("cp.async.wait_group 0;" ::: "memory");
            else                    asm volatile("cp.async.wait_group 1;" ::: "memory");
            __syncthreads();

            if (pfTile < NTILES) prefetch();

            const __half* As = smh + cs * STAGE_H;
            const __half* Bs = As + A_BUF;
            const __half* Ab = As + (wm * 32 + g) * LDSTR + 2 * t;
            const __half* Bb = Bs + (wn * 64 + g) * LDSTR + 2 * t;
            cs = (cs == 2) ? 0 : cs + 1;

#pragma unroll
            for (int s = 0; s < 4; s++) {
                const int kk = s * 16;
                uint32_t a[2][4], b[8][2];
#pragma unroll
                for (int mt = 0; mt < 2; mt++) {
                    const __half* p = Ab + mt * 16 * LDSTR + kk;
                    a[mt][0] = *(const uint32_t*)(p);
                    a[mt][1] = *(const uint32_t*)(p + 8 * LDSTR);
                    a[mt][2] = *(const uint32_t*)(p + 8);
                    a[mt][3] = *(const uint32_t*)(p + 8 * LDSTR + 8);
                }
#pragma unroll
                for (int nt = 0; nt < 8; nt++) {
                    const __half* p = Bb + nt * 8 * LDSTR + kk;
                    b[nt][0] = *(const uint32_t*)(p);
                    b[nt][1] = *(const uint32_t*)(p + 8);
                }
#pragma unroll
                for (int mt = 0; mt < 2; mt++)
#pragma unroll
                    for (int nt = 0; nt < 8; nt++)
                        mma_f16(acc[mt][nt], a[mt], b[nt]);
            }
        }

        // Epilogue (no smem, overlaps in-flight prefetches)
#pragma unroll
        for (int mt = 0; mt < 2; mt++) {
            const int r0 = m0 + wm * 32 + mt * 16 + g;
#pragma unroll
            for (int nt = 0; nt < 8; nt++) {
                const int col = n0 + wn * 64 + nt * 8 + 2 * t;
                const float b0 = __ldg(bias + col);
                const float b1 = __ldg(bias + col + 1);
                float2 v0 = make_float2(acc[mt][nt][0] + b0, acc[mt][nt][1] + b1);
                float2 v1 = make_float2(acc[mt][nt][2] + b0, acc[mt][nt][3] + b1);
                *(float2*)&out[(size_t)r0 * OUTF + col] = v0;
                *(float2*)&out[(size_t)(r0 + 8) * OUTF + col] = v1;
            }
        }
    }
}

extern "C" void kernel_launch(void* const* d_in, const int* in_sizes, int n_in,
                              void* d_out, int out_size) {
    const float* x = (const float*)d_in[0];
    const float* w = (const float*)d_in[1];
    const float* bias = (const float*)d_in[2];
    float* out = (float*)d_out;

    static int nsm = 0;
    if (nsm == 0) {
        int dev = 0;
        cudaGetDevice(&dev);
        cudaDeviceGetAttribute(&nsm, cudaDevAttrMultiProcessorCount, dev);
        cudaFuncSetAttribute(lin_gemm, cudaFuncAttributeMaxDynamicSharedMemorySize, SMEM_BYTES);
    }

    lin_reduce<<<2048, 256>>>(x, w);
    lin_gemm<<<2 * nsm, 256, SMEM_BYTES>>>(bias, out);
}

// round 9
// speedup vs baseline: 1.5237x; 1.0414x over previous
#include <cuda_runtime.h>
#include <cuda_fp16.h>
#include <cstdint>

#define H 4096
#define INF 4096
#define OUTF 4096
#define KRED 256
#define NRED 16

// Reduced operands in fp16. 2 MB each -> L2-resident through the GEMM.
__device__ __half g_xs[H * KRED];     // xs[m][k] row-major
__device__ __half g_wsT[OUTF * KRED]; // wsT[n][k] row-major

// ---------------------------------------------------------------------------
// Fused reduction. Inputs streamed with evict-first (.cs): no L2 pollution.
// ---------------------------------------------------------------------------
__device__ __forceinline__ float4 ldcs4(const float4* p) {
    float4 v;
    asm volatile("ld.global.cs.v4.f32 {%0,%1,%2,%3}, [%4];"
                 : "=f"(v.x), "=f"(v.y), "=f"(v.z), "=f"(v.w) : "l"(p));
    return v;
}

__global__ void __launch_bounds__(256) lin_reduce(const float* __restrict__ x,
                                                  const float* __restrict__ w) {
    int b = blockIdx.x;
    const float* src;
    __half* dst;
    if (b < 1024) { src = x; dst = g_xs; }
    else          { src = w; dst = g_wsT; b -= 1024; }
    const int row = b * 4 + (threadIdx.x >> 6);
    const int p = (threadIdx.x & 63) * 4;
    const float4* s = (const float4*)(src + (size_t)row * INF + p);
    float4 a0 = make_float4(0.f, 0.f, 0.f, 0.f);
    float4 a1 = make_float4(0.f, 0.f, 0.f, 0.f);
#pragma unroll
    for (int v = 0; v < NRED; v += 2) {
        float4 t0 = ldcs4(s + v * (KRED / 4));
        float4 t1 = ldcs4(s + (v + 1) * (KRED / 4));
        a0.x += t0.x; a0.y += t0.y; a0.z += t0.z; a0.w += t0.w;
        a1.x += t1.x; a1.y += t1.y; a1.z += t1.z; a1.w += t1.w;
    }
    a0.x += a1.x; a0.y += a1.y; a0.z += a1.z; a0.w += a1.w;
    __half2 lo = __floats2half2_rn(a0.x, a0.y);
    __half2 hi = __floats2half2_rn(a0.z, a0.w);
    uint2 pk = make_uint2(*(uint32_t*)&lo, *(uint32_t*)&hi);
    *(uint2*)(dst + (size_t)row * KRED + p) = pk;
}

// ---------------------------------------------------------------------------
// GEMM via mma.sync fp16: out = xs @ wsT^T + bias
// CTA 128(M) x 128(N); 256 threads, 8 warps 4x2; warp tile 32x64.
// KC=64, 4 chunks, 3-stage cp.async pipeline. 2 CTAs per SM.  (R7 verbatim)
// ---------------------------------------------------------------------------
#define BM 128
#define BN 128
#define KC 64
#define LDSTR 72                        // halves per smem row (144 B)
#define A_BUF (BM * LDSTR)              // 9216 halves
#define B_BUF (BN * LDSTR)              // 9216 halves
#define STAGE_H (A_BUF + B_BUF)         // 18432 halves
#define STAGE_B (STAGE_H * 2)           // 36864 bytes
#define SMEM_BYTES (3 * STAGE_B + 512)  // 111104 B -> 2 CTAs/SM

__device__ __forceinline__ void mma_f16(float* d, const uint32_t* a, const uint32_t* b) {
    asm volatile(
        "mma.sync.aligned.m16n8k16.row.col.f32.f16.f16.f32 "
        "{%0,%1,%2,%3}, {%4,%5,%6,%7}, {%8,%9}, {%0,%1,%2,%3};\n"
        : "+f"(d[0]), "+f"(d[1]), "+f"(d[2]), "+f"(d[3])
        : "r"(a[0]), "r"(a[1]), "r"(a[2]), "r"(a[3]),
          "r"(b[0]), "r"(b[1]));
}

__device__ __forceinline__ void cp16(uint32_t dst, const void* src) {
    asm volatile("cp.async.cg.shared.global [%0], [%1], 16;"
                 :: "r"(dst), "l"(src) : "memory");
}

__global__ void __launch_bounds__(256, 2)
lin_gemm(const float* __restrict__ bias, float* __restrict__ out) {
    extern __shared__ __half smh[];
    float* s_bias = (float*)(smh + 3 * STAGE_H);

    const int tid = threadIdx.x;
    const int warp = tid >> 5;
    const int lane = tid & 31;
    const int wm = warp >> 1;            // 0..3 -> 32-row slab
    const int wn = warp & 1;             // 0..1 -> 64-col slab
    const int g = lane >> 2;
    const int t = lane & 3;
    const int m0 = blockIdx.y * BM;
    const int n0 = blockIdx.x * BN;

    if (tid < 128) s_bias[tid] = bias[n0 + tid];

    const int lrow = tid >> 3;           // 0..31
    const int lch = (tid & 7) * 8;

    const uint32_t smem0 = (uint32_t)__cvta_generic_to_shared(smh);
    const uint32_t aDst0 = smem0 + (lrow * LDSTR + lch) * 2;
    const uint32_t bDst0 = smem0 + (A_BUF + lrow * LDSTR + lch) * 2;
    const __half* aSrc = g_xs + (size_t)(m0 + lrow) * KRED + lch;
    const __half* bSrc = g_wsT + (size_t)(n0 + lrow) * KRED + lch;

    float acc[2][8][4];
#pragma unroll
    for (int mt = 0; mt < 2; mt++)
#pragma unroll
        for (int nt = 0; nt < 8; nt++)
#pragma unroll
            for (int i = 0; i < 4; i++) acc[mt][nt][i] = 0.f;

#pragma unroll
    for (int pc = 0; pc < 2; pc++) {
        const uint32_t so = pc * STAGE_B;
        const int kc = pc * KC;
#pragma unroll
        for (int r = 0; r < 4; r++) {
            cp16(aDst0 + so + r * 32 * LDSTR * 2, aSrc + (size_t)r * 32 * KRED + kc);
            cp16(bDst0 + so + r * 32 * LDSTR * 2, bSrc + (size_t)r * 32 * KRED + kc);
        }
        asm volatile("cp.async.commit_group;" ::: "memory");
    }

#pragma unroll
    for (int c = 0; c < 4; c++) {
        if (c < 3) asm volatile("cp.async.wait_group 1;" ::: "memory");
        else       asm volatile("cp.async.wait_group 0;" ::: "memory");
        __syncthreads();

        if (c < 2) {
            const int ns = (c + 2) % 3;
            const uint32_t so = ns * STAGE_B;
            const int kc = (c + 2) * KC;
#pragma unroll
            for (int r = 0; r < 4; r++) {
                cp16(aDst0 + so + r * 32 * LDSTR * 2, aSrc + (size_t)r * 32 * KRED + kc);
                cp16(bDst0 + so + r * 32 * LDSTR * 2, bSrc + (size_t)r * 32 * KRED + kc);
            }
            asm volatile("cp.async.commit_group;" ::: "memory");
        }

        const __half* As = smh + (c % 3) * STAGE_H;
        const __half* Bs = As + A_BUF;
        const __half* Ab = As + (wm * 32 + g) * LDSTR + 2 * t;
        const __half* Bb = Bs + (wn * 64 + g) * LDSTR + 2 * t;

#pragma unroll
        for (int s = 0; s < 4; s++) {
            const int kk = s * 16;
            uint32_t a[2][4], b[8][2];
#pragma unroll
            for (int mt = 0; mt < 2; mt++) {
                const __half* p = Ab + mt * 16 * LDSTR + kk;
                a[mt][0] = *(const uint32_t*)(p);
                a[mt][1] = *(const uint32_t*)(p + 8 * LDSTR);
                a[mt][2] = *(const uint32_t*)(p + 8);
                a[mt][3] = *(const uint32_t*)(p + 8 * LDSTR + 8);
            }
#pragma unroll
            for (int nt = 0; nt < 8; nt++) {
                const __half* p = Bb + nt * 8 * LDSTR + kk;
                b[nt][0] = *(const uint32_t*)(p);
                b[nt][1] = *(const uint32_t*)(p + 8);
            }
#pragma unroll
            for (int mt = 0; mt < 2; mt++)
#pragma unroll
                for (int nt = 0; nt < 8; nt++)
                    mma_f16(acc[mt][nt], a[mt], b[nt]);
        }
    }

#pragma unroll
    for (int mt = 0; mt < 2; mt++) {
        const int r0 = m0 + wm * 32 + mt * 16 + g;
#pragma unroll
        for (int nt = 0; nt < 8; nt++) {
            const int col = wn * 64 + nt * 8 + 2 * t;
            const float b0 = s_bias[col], b1 = s_bias[col + 1];
            float2 v0 = make_float2(acc[mt][nt][0] + b0, acc[mt][nt][1] + b1);
            float2 v1 = make_float2(acc[mt][nt][2] + b0, acc[mt][nt][3] + b1);
            *(float2*)&out[(size_t)r0 * OUTF + n0 + col] = v0;
            *(float2*)&out[(size_t)(r0 + 8) * OUTF + n0 + col] = v1;
        }
    }
}

extern "C" void kernel_launch(void* const* d_in, const int* in_sizes, int n_in,
                              void* d_out, int out_size) {
    const float* x = (const float*)d_in[0];
    const float* w = (const float*)d_in[1];
    const float* bias = (const float*)d_in[2];
    float* out = (float*)d_out;

    cudaFuncSetAttribute(lin_gemm, cudaFuncAttributeMaxDynamicSharedMemorySize, SMEM_BYTES);

    lin_reduce<<<2048, 256>>>(x, w);
    dim3 grid(OUTF / BN, H / BM);   // (32, 32)
    lin_gemm<<<grid, 256, SMEM_BYTES>>>(bias, out);
}

// round 10
// speedup vs baseline: 1.5667x; 1.0282x over previous
#include <cuda_runtime.h>
#include <cuda_fp16.h>
#include <cstdint>

#define H 4096
#define INF 4096
#define OUTF 4096
#define KRED 256
#define NRED 16

// Reduced operands in fp16. 2 MB each -> L2-resident through the GEMM.
__device__ __half g_xs[H * KRED];     // xs[m][k] row-major
__device__ __half g_wsT[OUTF * KRED]; // wsT[n][k] row-major

// ---------------------------------------------------------------------------
// Fused reduction. Inputs streamed with evict-first (.cs).
// ---------------------------------------------------------------------------
__device__ __forceinline__ float4 ldcs4(const float4* p) {
    float4 v;
    asm volatile("ld.global.cs.v4.f32 {%0,%1,%2,%3}, [%4];"
                 : "=f"(v.x), "=f"(v.y), "=f"(v.z), "=f"(v.w) : "l"(p));
    return v;
}

__global__ void __launch_bounds__(256) lin_reduce(const float* __restrict__ x,
                                                  const float* __restrict__ w) {
    int b = blockIdx.x;
    const float* src;
    __half* dst;
    if (b < 1024) { src = x; dst = g_xs; }
    else          { src = w; dst = g_wsT; b -= 1024; }
    const int row = b * 4 + (threadIdx.x >> 6);
    const int p = (threadIdx.x & 63) * 4;
    const float4* s = (const float4*)(src + (size_t)row * INF + p);
    float4 a0 = make_float4(0.f, 0.f, 0.f, 0.f);
    float4 a1 = make_float4(0.f, 0.f, 0.f, 0.f);
#pragma unroll
    for (int v = 0; v < NRED; v += 2) {
        float4 t0 = ldcs4(s + v * (KRED / 4));
        float4 t1 = ldcs4(s + (v + 1) * (KRED / 4));
        a0.x += t0.x; a0.y += t0.y; a0.z += t0.z; a0.w += t0.w;
        a1.x += t1.x; a1.y += t1.y; a1.z += t1.z; a1.w += t1.w;
    }
    a0.x += a1.x; a0.y += a1.y; a0.z += a1.z; a0.w += a1.w;
    __half2 lo = __floats2half2_rn(a0.x, a0.y);
    __half2 hi = __floats2half2_rn(a0.z, a0.w);
    uint2 pk = make_uint2(*(uint32_t*)&lo, *(uint32_t*)&hi);
    *(uint2*)(dst + (size_t)row * KRED + p) = pk;
}

// ---------------------------------------------------------------------------
// GEMM via mma.sync fp16 + ldmatrix: out = xs @ wsT^T + bias
// CTA 128x128; 256 threads, 8 warps 4x2; warp tile 32x64.
// KC=64, 4 chunks, 3-stage cp.async pipeline. 2 CTAs per SM.
// ---------------------------------------------------------------------------
#define BM 128
#define BN 128
#define KC 64
#define LDSTR 72                        // halves per smem row (144 B)
#define A_BUF (BM * LDSTR)
#define B_BUF (BN * LDSTR)
#define STAGE_H (A_BUF + B_BUF)
#define STAGE_B (STAGE_H * 2)           // 36864 bytes
#define SMEM_BYTES (3 * STAGE_B + 512)  // 111104 B -> 2 CTAs/SM

__device__ __forceinline__ void mma_f16(float* d, const uint32_t* a, const uint32_t* b) {
    asm volatile(
        "mma.sync.aligned.m16n8k16.row.col.f32.f16.f16.f32 "
        "{%0,%1,%2,%3}, {%4,%5,%6,%7}, {%8,%9}, {%0,%1,%2,%3};\n"
        : "+f"(d[0]), "+f"(d[1]), "+f"(d[2]), "+f"(d[3])
        : "r"(a[0]), "r"(a[1]), "r"(a[2]), "r"(a[3]),
          "r"(b[0]), "r"(b[1]));
}

__device__ __forceinline__ void cp16(uint32_t dst, const void* src) {
    asm volatile("cp.async.cg.shared.global [%0], [%1], 16;"
                 :: "r"(dst), "l"(src) : "memory");
}

__device__ __forceinline__ void ldm_x4(uint32_t& r0, uint32_t& r1, uint32_t& r2,
                                       uint32_t& r3, uint32_t addr) {
    asm volatile("ldmatrix.sync.aligned.m8n8.x4.shared.b16 {%0,%1,%2,%3}, [%4];"
                 : "=r"(r0), "=r"(r1), "=r"(r2), "=r"(r3) : "r"(addr));
}

__global__ void __launch_bounds__(256, 2)
lin_gemm(const float* __restrict__ bias, float* __restrict__ out) {
    extern __shared__ __half smh[];
    float* s_bias = (float*)(smh + 3 * STAGE_H);

    const int tid = threadIdx.x;
    const int warp = tid >> 5;
    const int lane = tid & 31;
    const int wm = warp >> 1;            // 0..3 -> 32-row slab
    const int wn = warp & 1;             // 0..1 -> 64-col slab
    const int g = lane >> 2;
    const int t = lane & 3;
    const int m0 = blockIdx.y * BM;
    const int n0 = blockIdx.x * BN;

    if (tid < 128) s_bias[tid] = bias[n0 + tid];

    const int lrow = tid >> 3;           // 0..31
    const int lch = (tid & 7) * 8;

    const uint32_t smem0 = (uint32_t)__cvta_generic_to_shared(smh);
    const uint32_t aDst0 = smem0 + (lrow * LDSTR + lch) * 2;
    const uint32_t bDst0 = smem0 + (A_BUF + lrow * LDSTR + lch) * 2;
    const __half* aSrc = g_xs + (size_t)(m0 + lrow) * KRED + lch;
    const __half* bSrc = g_wsT + (size_t)(n0 + lrow) * KRED + lch;

    // ldmatrix per-lane offsets (bytes, relative to stage base)
    // A x4 tiles: lanes 0-7 (m0-7,k0-7), 8-15 (m8-15,k0-7), 16-23 (m0-7,k8-15), 24-31 (m8-15,k8-15)
    const int aRow = (lane & 7) + ((lane >> 3) & 1) * 8;
    const int aK = (lane >> 4) * 8;
    const uint32_t aLdmOff = ((wm * 32 + aRow) * LDSTR + aK) * 2;
    // B x4 tiles: (n0-7,k0-7), (n0-7,k8-15), (n8-15,k0-7), (n8-15,k8-15)
    const int bRow = (lane & 7) + ((lane >> 4) & 1) * 8;
    const int bK = ((lane >> 3) & 1) * 8;
    const uint32_t bLdmOff = (uint32_t)(A_BUF * 2) + ((wn * 64 + bRow) * LDSTR + bK) * 2;

    float acc[2][8][4];
#pragma unroll
    for (int mt = 0; mt < 2; mt++)
#pragma unroll
        for (int nt = 0; nt < 8; nt++)
#pragma unroll
            for (int i = 0; i < 4; i++) acc[mt][nt][i] = 0.f;

#pragma unroll
    for (int pc = 0; pc < 2; pc++) {
        const uint32_t so = pc * STAGE_B;
        const int kc = pc * KC;
#pragma unroll
        for (int r = 0; r < 4; r++) {
            cp16(aDst0 + so + r * 32 * LDSTR * 2, aSrc + (size_t)r * 32 * KRED + kc);
            cp16(bDst0 + so + r * 32 * LDSTR * 2, bSrc + (size_t)r * 32 * KRED + kc);
        }
        asm volatile("cp.async.commit_group;" ::: "memory");
    }

#pragma unroll
    for (int c = 0; c < 4; c++) {
        if (c < 3) asm volatile("cp.async.wait_group 1;" ::: "memory");
        else       asm volatile("cp.async.wait_group 0;" ::: "memory");
        __syncthreads();

        if (c < 2) {
            const int ns = (c + 2) % 3;
            const uint32_t so = ns * STAGE_B;
            const int kc = (c + 2) * KC;
#pragma unroll
            for (int r = 0; r < 4; r++) {
                cp16(aDst0 + so + r * 32 * LDSTR * 2, aSrc + (size_t)r * 32 * KRED + kc);
                cp16(bDst0 + so + r * 32 * LDSTR * 2, bSrc + (size_t)r * 32 * KRED + kc);
            }
            asm volatile("cp.async.commit_group;" ::: "memory");
        }

        const uint32_t stageBase = smem0 + (c % 3) * STAGE_B;
        const uint32_t aAddr = stageBase + aLdmOff;
        const uint32_t bAddr = stageBase + bLdmOff;

#pragma unroll
        for (int s = 0; s < 4; s++) {
            const int kkB = s * 16 * 2;   // byte offset of k16 step
            uint32_t a[2][4], b[8][2];
#pragma unroll
            for (int mt = 0; mt < 2; mt++)
                ldm_x4(a[mt][0], a[mt][1], a[mt][2], a[mt][3],
                       aAddr + mt * 16 * LDSTR * 2 + kkB);
#pragma unroll
            for (int np = 0; np < 4; np++)
                ldm_x4(b[2 * np][0], b[2 * np][1], b[2 * np + 1][0], b[2 * np + 1][1],
                       bAddr + np * 16 * LDSTR * 2 + kkB);
#pragma unroll
            for (int mt = 0; mt < 2; mt++)
#pragma unroll
                for (int nt = 0; nt < 8; nt++)
                    mma_f16(acc[mt][nt], a[mt], b[nt]);
        }
    }

#pragma unroll
    for (int mt = 0; mt < 2; mt++) {
        const int r0 = m0 + wm * 32 + mt * 16 + g;
#pragma unroll
        for (int nt = 0; nt < 8; nt++) {
            const int col = wn * 64 + nt * 8 + 2 * t;
            const float b0 = s_bias[col], b1 = s_bias[col + 1];
            float2 v0 = make_float2(acc[mt][nt][0] + b0, acc[mt][nt][1] + b1);
            float2 v1 = make_float2(acc[mt][nt][2] + b0, acc[mt][nt][3] + b1);
            *(float2*)&out[(size_t)r0 * OUTF + n0 + col] = v0;
            *(float2*)&out[(size_t)(r0 + 8) * OUTF + n0 + col] = v1;
        }
    }
}

extern "C" void kernel_launch(void* const* d_in, const int* in_sizes, int n_in,
                              void* d_out, int out_size) {
    const float* x = (const float*)d_in[0];
    const float* w = (const float*)d_in[1];
    const float* bias = (const float*)d_in[2];
    float* out = (float*)d_out;

    cudaFuncSetAttribute(lin_gemm, cudaFuncAttributeMaxDynamicSharedMemorySize, SMEM_BYTES);

    lin_reduce<<<2048, 256>>>(x, w);
    dim3 grid(OUTF / BN, H / BM);   // (32, 32)
    lin_gemm<<<grid, 256, SMEM_BYTES>>>(bias, out);
}